// round 1
// baseline (speedup 1.0000x reference)
#include <cuda_runtime.h>

#define N_NODES 50000
#define N_EDGES 800000
#define F_IN 128
#define F_HID 256
#define F_OUT 64

// ---------------- scratch (static device allocations; no cudaMalloc) -------
__device__ __align__(16) float g_agg1[N_NODES * F_IN];    // 25.6 MB
__device__ __align__(16) float g_h[N_NODES * F_HID];      // 51.2 MB
__device__ __align__(16) float g_p[N_NODES * F_OUT];      // 12.8 MB  (h @ W_l2, pre-aggregation)
__device__ __align__(16) float g_agg2[N_NODES * F_OUT];   // 12.8 MB
__device__ __align__(16) float g_deg[N_NODES];

// ---------------- helpers ---------------------------------------------------
__device__ __forceinline__ void red_add_v4(float* p, float4 v) {
    asm volatile("red.global.add.v4.f32 [%0], {%1,%2,%3,%4};"
                 :: "l"(p), "f"(v.x), "f"(v.y), "f"(v.z), "f"(v.w) : "memory");
}

// ---------------- zero scratch ----------------------------------------------
__global__ void zero_kernel() {
    int idx = blockIdx.x * blockDim.x + threadIdx.x;
    const int n1 = N_NODES * F_IN / 4;     // 1,600,000 float4
    const int n2 = N_NODES * F_OUT / 4;    //   800,000 float4
    const int n3 = N_NODES / 4;            //    12,500 float4
    float4 z = make_float4(0.f, 0.f, 0.f, 0.f);
    if (idx < n1)                ((float4*)g_agg1)[idx] = z;
    else if (idx < n1 + n2)      ((float4*)g_agg2)[idx - n1] = z;
    else if (idx < n1 + n2 + n3) ((float4*)g_deg)[idx - n1 - n2] = z;
}

// ---------------- layer-1 scatter: agg1[dst] += x[src]; deg[dst]++ ----------
// one warp per edge; lane handles one float4 of the 128-float row
__global__ void scatter1_kernel(const float* __restrict__ x, const int* __restrict__ ei) {
    int t = blockIdx.x * blockDim.x + threadIdx.x;
    int e = t >> 5;
    int lane = t & 31;
    if (e >= N_EDGES) return;
    int src = ei[e];
    int dst = ei[N_EDGES + e];
    float4 v = ((const float4*)x)[src * (F_IN / 4) + lane];
    red_add_v4(g_agg1 + dst * F_IN + lane * 4, v);
    if (lane == 0) atomicAdd(&g_deg[dst], 1.0f);
}

// ---------------- scale agg1 rows by 1/max(deg,1) ---------------------------
__global__ void scale1_kernel() {
    int idx = blockIdx.x * blockDim.x + threadIdx.x;
    if (idx >= N_NODES * (F_IN / 4)) return;
    int row = idx >> 5;
    float inv = 1.0f / fmaxf(g_deg[row], 1.0f);
    float4 v = ((float4*)g_agg1)[idx];
    v.x *= inv; v.y *= inv; v.z *= inv; v.w *= inv;
    ((float4*)g_agg1)[idx] = v;
}

// ---------------- GEMM 1: h = relu([agg1 | x] @ [W_l1 ; W_r1] + b1) ---------
// fp32 via packed fma.rn.f32x2 (FFMA2) for 2x FP32 throughput.
// BM=64 rows, BN=128 cols, BK=16, 256 threads, thread tile 4 rows x 8 cols.
#define BM 64
#define BN 128
#define BK 16

__global__ __launch_bounds__(256) void gemm1_kernel(
    const float* __restrict__ x, const float* __restrict__ Wl,
    const float* __restrict__ Wr, const float* __restrict__ bias)
{
    __shared__ float As[BK][BM];
    __shared__ float Bs[BK][BN];
    const int tid = threadIdx.x;
    const int row_base = blockIdx.x * BM;
    const int col_base = blockIdx.y * BN;
    const int tx = tid & 15;   // col group (8 cols)
    const int ty = tid >> 4;   // row group (4 rows)

    unsigned long long acc[4][4];   // 4 rows x 4 col-pairs (packed f32x2)
#pragma unroll
    for (int i = 0; i < 4; i++)
#pragma unroll
        for (int j = 0; j < 4; j++) acc[i][j] = 0ULL;

    const int am = tid >> 2;          // A-load row within tile
    const int ak = (tid & 3) * 4;     // A-load k offset (float4)
    const int arow = row_base + am;

    for (int k0 = 0; k0 < 2 * F_IN; k0 += BK) {
        // --- A tile: concat [agg1(scaled) | x], row-major, K fast ---
        {
            int gk = k0 + ak;
            float4 v = make_float4(0.f, 0.f, 0.f, 0.f);
            if (arow < N_NODES) {
                const float* s = (gk < F_IN) ? (g_agg1 + arow * F_IN + gk)
                                             : (x + arow * F_IN + (gk - F_IN));
                v = *(const float4*)s;
            }
            As[ak][am] = v.x; As[ak + 1][am] = v.y;
            As[ak + 2][am] = v.z; As[ak + 3][am] = v.w;
        }
        // --- B tile: concat [W_l1 ; W_r1] ---
#pragma unroll
        for (int it = 0; it < 2; it++) {
            int f = tid + it * 256;
            int bk = f >> 5;
            int bc = (f & 31) * 4;
            int gk = k0 + bk;
            int j = col_base + bc;
            const float* s = (gk < F_IN) ? (Wl + gk * F_HID + j)
                                         : (Wr + (gk - F_IN) * F_HID + j);
            *(float4*)&Bs[bk][bc] = *(const float4*)s;
        }
        __syncthreads();
#pragma unroll
        for (int kk = 0; kk < BK; kk++) {
            float4 av  = *(const float4*)&As[kk][ty * 4];
            float4 bv0 = *(const float4*)&Bs[kk][tx * 8];
            float4 bv1 = *(const float4*)&Bs[kk][tx * 8 + 4];
            unsigned long long bp[4];
            asm("mov.b64 %0, {%1,%2};" : "=l"(bp[0]) : "f"(bv0.x), "f"(bv0.y));
            asm("mov.b64 %0, {%1,%2};" : "=l"(bp[1]) : "f"(bv0.z), "f"(bv0.w));
            asm("mov.b64 %0, {%1,%2};" : "=l"(bp[2]) : "f"(bv1.x), "f"(bv1.y));
            asm("mov.b64 %0, {%1,%2};" : "=l"(bp[3]) : "f"(bv1.z), "f"(bv1.w));
            float a4[4] = {av.x, av.y, av.z, av.w};
#pragma unroll
            for (int i = 0; i < 4; i++) {
                unsigned long long aa;
                asm("mov.b64 %0, {%1,%1};" : "=l"(aa) : "f"(a4[i]));
#pragma unroll
                for (int j = 0; j < 4; j++)
                    asm("fma.rn.f32x2 %0, %1, %2, %0;" : "+l"(acc[i][j]) : "l"(aa), "l"(bp[j]));
            }
        }
        __syncthreads();
    }
    // epilogue: + bias, relu, store
#pragma unroll
    for (int i = 0; i < 4; i++) {
        int row = row_base + ty * 4 + i;
        if (row >= N_NODES) continue;
#pragma unroll
        for (int j = 0; j < 4; j++) {
            float lo, hi;
            asm("mov.b64 {%0,%1}, %2;" : "=f"(lo), "=f"(hi) : "l"(acc[i][j]));
            int c = col_base + tx * 8 + 2 * j;
            lo = fmaxf(lo + bias[c], 0.f);
            hi = fmaxf(hi + bias[c + 1], 0.f);
            *(float2*)&g_h[row * F_HID + c] = make_float2(lo, hi);
        }
    }
}

// ---------------- GEMM 2: [p | r] = h @ [W_l2 | W_r2] -----------------------
// p -> g_p (to be aggregated), r -> d_out (raw, pre-sigmoid)
__global__ __launch_bounds__(256) void gemm2_kernel(
    const float* __restrict__ Wl, const float* __restrict__ Wr,
    float* __restrict__ r_out)
{
    __shared__ float As[BK][BM];
    __shared__ float Bs[BK][BN];
    const int tid = threadIdx.x;
    const int row_base = blockIdx.x * BM;
    const int tx = tid & 15;
    const int ty = tid >> 4;

    unsigned long long acc[4][4];
#pragma unroll
    for (int i = 0; i < 4; i++)
#pragma unroll
        for (int j = 0; j < 4; j++) acc[i][j] = 0ULL;

    const int am = tid >> 2;
    const int ak = (tid & 3) * 4;
    const int arow = row_base + am;

    for (int k0 = 0; k0 < F_HID; k0 += BK) {
        {
            int gk = k0 + ak;
            float4 v = make_float4(0.f, 0.f, 0.f, 0.f);
            if (arow < N_NODES)
                v = *(const float4*)(g_h + arow * F_HID + gk);
            As[ak][am] = v.x; As[ak + 1][am] = v.y;
            As[ak + 2][am] = v.z; As[ak + 3][am] = v.w;
        }
#pragma unroll
        for (int it = 0; it < 2; it++) {
            int f = tid + it * 256;
            int bk = f >> 5;
            int bc = (f & 31) * 4;   // col 0..127 (step 4)
            int gk = k0 + bk;
            const float* s = (bc < F_OUT) ? (Wl + gk * F_OUT + bc)
                                          : (Wr + gk * F_OUT + (bc - F_OUT));
            *(float4*)&Bs[bk][bc] = *(const float4*)s;
        }
        __syncthreads();
#pragma unroll
        for (int kk = 0; kk < BK; kk++) {
            float4 av  = *(const float4*)&As[kk][ty * 4];
            float4 bv0 = *(const float4*)&Bs[kk][tx * 8];
            float4 bv1 = *(const float4*)&Bs[kk][tx * 8 + 4];
            unsigned long long bp[4];
            asm("mov.b64 %0, {%1,%2};" : "=l"(bp[0]) : "f"(bv0.x), "f"(bv0.y));
            asm("mov.b64 %0, {%1,%2};" : "=l"(bp[1]) : "f"(bv0.z), "f"(bv0.w));
            asm("mov.b64 %0, {%1,%2};" : "=l"(bp[2]) : "f"(bv1.x), "f"(bv1.y));
            asm("mov.b64 %0, {%1,%2};" : "=l"(bp[3]) : "f"(bv1.z), "f"(bv1.w));
            float a4[4] = {av.x, av.y, av.z, av.w};
#pragma unroll
            for (int i = 0; i < 4; i++) {
                unsigned long long aa;
                asm("mov.b64 %0, {%1,%1};" : "=l"(aa) : "f"(a4[i]));
#pragma unroll
                for (int j = 0; j < 4; j++)
                    asm("fma.rn.f32x2 %0, %1, %2, %0;" : "+l"(acc[i][j]) : "l"(aa), "l"(bp[j]));
            }
        }
        __syncthreads();
    }
#pragma unroll
    for (int i = 0; i < 4; i++) {
        int row = row_base + ty * 4 + i;
        if (row >= N_NODES) continue;
#pragma unroll
        for (int j = 0; j < 4; j++) {
            float lo, hi;
            asm("mov.b64 {%0,%1}, %2;" : "=f"(lo), "=f"(hi) : "l"(acc[i][j]));
            int c = tx * 8 + 2 * j;   // 0..126, pair never crosses 64
            if (c < F_OUT)
                *(float2*)&g_p[row * F_OUT + c] = make_float2(lo, hi);
            else
                *(float2*)&r_out[row * F_OUT + (c - F_OUT)] = make_float2(lo, hi);
        }
    }
}

// ---------------- layer-2 scatter: agg2[dst] += p[src] ----------------------
// 16 float4 chunks per edge (64 floats); 16 threads per edge
__global__ void scatter2_kernel(const int* __restrict__ ei) {
    int t = blockIdx.x * blockDim.x + threadIdx.x;
    int e = t >> 4;
    int c = t & 15;
    if (e >= N_EDGES) return;
    int src = ei[e];
    int dst = ei[N_EDGES + e];
    float4 v = ((const float4*)g_p)[src * (F_OUT / 4) + c];
    red_add_v4(g_agg2 + dst * F_OUT + c * 4, v);
}

// ---------------- finalize: out = sigmoid(agg2/deg + r + b2) ----------------
__global__ void finalize_kernel(const float* __restrict__ b2, float* __restrict__ out) {
    int idx = blockIdx.x * blockDim.x + threadIdx.x;
    if (idx >= N_NODES * F_OUT) return;
    int n = idx >> 6;
    int j = idx & 63;
    float inv = 1.0f / fmaxf(g_deg[n], 1.0f);
    float z = g_agg2[idx] * inv + out[idx] + b2[j];
    out[idx] = 1.0f / (1.0f + expf(-z));
}

// ---------------- launch -----------------------------------------------------
extern "C" void kernel_launch(void* const* d_in, const int* in_sizes, int n_in,
                              void* d_out, int out_size) {
    const float* x   = (const float*)d_in[0];
    const int*   ei  = (const int*)d_in[1];
    const float* Wl1 = (const float*)d_in[2];
    const float* Wr1 = (const float*)d_in[3];
    const float* b1  = (const float*)d_in[4];
    const float* Wl2 = (const float*)d_in[5];
    const float* Wr2 = (const float*)d_in[6];
    const float* b2  = (const float*)d_in[7];
    float* out = (float*)d_out;

    {
        int tot = N_NODES * F_IN / 4 + N_NODES * F_OUT / 4 + N_NODES / 4;
        zero_kernel<<<(tot + 255) / 256, 256>>>();
    }
    scatter1_kernel<<<(N_EDGES * 32) / 256, 256>>>(x, ei);
    scale1_kernel<<<(N_NODES * (F_IN / 4) + 255) / 256, 256>>>();
    {
        dim3 g((N_NODES + BM - 1) / BM, F_HID / BN);
        gemm1_kernel<<<g, 256>>>(x, Wl1, Wr1, b1);
    }
    {
        dim3 g((N_NODES + BM - 1) / BM, 1);
        gemm2_kernel<<<g, 256>>>(Wl2, Wr2, out);
    }
    scatter2_kernel<<<(N_EDGES * 16) / 256, 256>>>(ei);
    finalize_kernel<<<(N_NODES * F_OUT + 255) / 256, 256>>>(b2, out);
}

// round 2
// speedup vs baseline: 1.2240x; 1.2240x over previous
#include <cuda_runtime.h>

#define N_NODES 50000
#define N_EDGES 800000
#define F_IN 128
#define F_HID 256
#define F_OUT 64

// ---------------- scratch (static device allocations; no cudaMalloc) -------
__device__ __align__(16) float g_agg1[N_NODES * F_IN];    // 25.6 MB (raw sums)
__device__ __align__(16) float g_h[N_NODES * F_HID];      // 51.2 MB
__device__ __align__(16) float g_p[N_NODES * F_OUT];      // 12.8 MB  (h @ W_l2)
__device__ __align__(16) float g_agg2[N_NODES * F_OUT];   // 12.8 MB
__device__ __align__(16) float g_deg[N_NODES];

// ---------------- helpers ---------------------------------------------------
__device__ __forceinline__ void red_add_v4(float* p, float4 v) {
    asm volatile("red.global.add.v4.f32 [%0], {%1,%2,%3,%4};"
                 :: "l"(p), "f"(v.x), "f"(v.y), "f"(v.z), "f"(v.w) : "memory");
}

// ---------------- zero scratch ----------------------------------------------
__global__ void zero_kernel() {
    int idx = blockIdx.x * blockDim.x + threadIdx.x;
    const int n1 = N_NODES * F_IN / 4;
    const int n2 = N_NODES * F_OUT / 4;
    const int n3 = N_NODES / 4;
    float4 z = make_float4(0.f, 0.f, 0.f, 0.f);
    if (idx < n1)                ((float4*)g_agg1)[idx] = z;
    else if (idx < n1 + n2)      ((float4*)g_agg2)[idx - n1] = z;
    else if (idx < n1 + n2 + n3) ((float4*)g_deg)[idx - n1 - n2] = z;
}

// ---------------- layer-1 scatter: agg1[dst] += x[src]; deg[dst]++ ----------
__global__ void scatter1_kernel(const float* __restrict__ x, const int* __restrict__ ei) {
    int t = blockIdx.x * blockDim.x + threadIdx.x;
    int e = t >> 5;
    int lane = t & 31;
    if (e >= N_EDGES) return;
    int src = ei[e];
    int dst = ei[N_EDGES + e];
    float4 v = ((const float4*)x)[src * (F_IN / 4) + lane];
    red_add_v4(g_agg1 + dst * F_IN + lane * 4, v);
    if (lane == 0) atomicAdd(&g_deg[dst], 1.0f);
}

// ---------------- GEMM tiles ------------------------------------------------
// BM=128, BN=128, BK=16, 256 threads, thread tile 8 rows x 8 cols (4 f32x2 pairs)
// Balanced: per kk per SM-block: 256 fma2 warp-instr (128cyc @2/cyc) vs
// 16 KB LDS (128 cyc @128B/cyc).
#define BM 128
#define BN 128
#define BK 16
#define AS_LD (BM + 4)

// GEMM 1: h = relu([agg1/deg | x] @ [W_l1 ; W_r1] + b1)
__global__ __launch_bounds__(256, 2) void gemm1_kernel(
    const float* __restrict__ x, const float* __restrict__ Wl,
    const float* __restrict__ Wr, const float* __restrict__ bias)
{
    __shared__ float As[BK][AS_LD];
    __shared__ float Bs[BK][BN];
    const int tid = threadIdx.x;
    const int row_base = blockIdx.x * BM;
    const int col_base = blockIdx.y * BN;
    const int tx = tid & 15;   // 16 col groups of 8
    const int ty = tid >> 4;   // 16 row groups of 8

    unsigned long long acc[8][4];
#pragma unroll
    for (int i = 0; i < 8; i++)
#pragma unroll
        for (int j = 0; j < 4; j++) acc[i][j] = 0ULL;

    const int ak = (tid & 3) * 4;   // A-load k offset
    const int am0 = tid >> 2;       // A-load row (+64 on second it)

    for (int k0 = 0; k0 < 2 * F_IN; k0 += BK) {
        // --- A tile: concat [agg1*inv_deg | x] ---
#pragma unroll
        for (int it = 0; it < 2; it++) {
            int am = am0 + it * 64;
            int arow = row_base + am;
            int gk = k0 + ak;
            float4 v = make_float4(0.f, 0.f, 0.f, 0.f);
            if (arow < N_NODES) {
                if (gk < F_IN) {
                    v = *(const float4*)(g_agg1 + arow * F_IN + gk);
                    float inv = 1.0f / fmaxf(g_deg[arow], 1.0f);
                    v.x *= inv; v.y *= inv; v.z *= inv; v.w *= inv;
                } else {
                    v = *(const float4*)(x + arow * F_IN + (gk - F_IN));
                }
            }
            As[ak][am] = v.x; As[ak + 1][am] = v.y;
            As[ak + 2][am] = v.z; As[ak + 3][am] = v.w;
        }
        // --- B tile: concat [W_l1 ; W_r1] ---
#pragma unroll
        for (int it = 0; it < 2; it++) {
            int f = tid + it * 256;
            int bk = f >> 5;
            int bc = (f & 31) * 4;
            int gk = k0 + bk;
            int j = col_base + bc;
            const float* s = (gk < F_IN) ? (Wl + gk * F_HID + j)
                                         : (Wr + (gk - F_IN) * F_HID + j);
            *(float4*)&Bs[bk][bc] = *(const float4*)s;
        }
        __syncthreads();
#pragma unroll
        for (int kk = 0; kk < BK; kk++) {
            float4 a0 = *(const float4*)&As[kk][ty * 8];
            float4 a1 = *(const float4*)&As[kk][ty * 8 + 4];
            ulonglong2 bq0 = *(const ulonglong2*)&Bs[kk][tx * 8];
            ulonglong2 bq1 = *(const ulonglong2*)&Bs[kk][tx * 8 + 4];
            unsigned long long bp[4] = {bq0.x, bq0.y, bq1.x, bq1.y};
            float a[8] = {a0.x, a0.y, a0.z, a0.w, a1.x, a1.y, a1.z, a1.w};
#pragma unroll
            for (int i = 0; i < 8; i++) {
                unsigned long long aa;
                asm("mov.b64 %0, {%1,%1};" : "=l"(aa) : "f"(a[i]));
#pragma unroll
                for (int j = 0; j < 4; j++)
                    asm("fma.rn.f32x2 %0, %1, %2, %0;" : "+l"(acc[i][j]) : "l"(aa), "l"(bp[j]));
            }
        }
        __syncthreads();
    }
    // epilogue: + bias, relu, store
#pragma unroll
    for (int i = 0; i < 8; i++) {
        int row = row_base + ty * 8 + i;
        if (row >= N_NODES) continue;
#pragma unroll
        for (int j = 0; j < 4; j++) {
            float lo, hi;
            asm("mov.b64 {%0,%1}, %2;" : "=f"(lo), "=f"(hi) : "l"(acc[i][j]));
            int c = col_base + tx * 8 + 2 * j;
            lo = fmaxf(lo + bias[c], 0.f);
            hi = fmaxf(hi + bias[c + 1], 0.f);
            *(float2*)&g_h[row * F_HID + c] = make_float2(lo, hi);
        }
    }
}

// GEMM 2: [p | r] = h @ [W_l2 | W_r2];  p -> g_p, r -> d_out (pre-sigmoid)
__global__ __launch_bounds__(256, 2) void gemm2_kernel(
    const float* __restrict__ Wl, const float* __restrict__ Wr,
    float* __restrict__ r_out)
{
    __shared__ float As[BK][AS_LD];
    __shared__ float Bs[BK][BN];
    const int tid = threadIdx.x;
    const int row_base = blockIdx.x * BM;
    const int tx = tid & 15;
    const int ty = tid >> 4;

    unsigned long long acc[8][4];
#pragma unroll
    for (int i = 0; i < 8; i++)
#pragma unroll
        for (int j = 0; j < 4; j++) acc[i][j] = 0ULL;

    const int ak = (tid & 3) * 4;
    const int am0 = tid >> 2;

    for (int k0 = 0; k0 < F_HID; k0 += BK) {
#pragma unroll
        for (int it = 0; it < 2; it++) {
            int am = am0 + it * 64;
            int arow = row_base + am;
            int gk = k0 + ak;
            float4 v = make_float4(0.f, 0.f, 0.f, 0.f);
            if (arow < N_NODES)
                v = *(const float4*)(g_h + arow * F_HID + gk);
            As[ak][am] = v.x; As[ak + 1][am] = v.y;
            As[ak + 2][am] = v.z; As[ak + 3][am] = v.w;
        }
#pragma unroll
        for (int it = 0; it < 2; it++) {
            int f = tid + it * 256;
            int bk = f >> 5;
            int bc = (f & 31) * 4;
            int gk = k0 + bk;
            const float* s = (bc < F_OUT) ? (Wl + gk * F_OUT + bc)
                                          : (Wr + gk * F_OUT + (bc - F_OUT));
            *(float4*)&Bs[bk][bc] = *(const float4*)s;
        }
        __syncthreads();
#pragma unroll
        for (int kk = 0; kk < BK; kk++) {
            float4 a0 = *(const float4*)&As[kk][ty * 8];
            float4 a1 = *(const float4*)&As[kk][ty * 8 + 4];
            ulonglong2 bq0 = *(const ulonglong2*)&Bs[kk][tx * 8];
            ulonglong2 bq1 = *(const ulonglong2*)&Bs[kk][tx * 8 + 4];
            unsigned long long bp[4] = {bq0.x, bq0.y, bq1.x, bq1.y};
            float a[8] = {a0.x, a0.y, a0.z, a0.w, a1.x, a1.y, a1.z, a1.w};
#pragma unroll
            for (int i = 0; i < 8; i++) {
                unsigned long long aa;
                asm("mov.b64 %0, {%1,%1};" : "=l"(aa) : "f"(a[i]));
#pragma unroll
                for (int j = 0; j < 4; j++)
                    asm("fma.rn.f32x2 %0, %1, %2, %0;" : "+l"(acc[i][j]) : "l"(aa), "l"(bp[j]));
            }
        }
        __syncthreads();
    }
#pragma unroll
    for (int i = 0; i < 8; i++) {
        int row = row_base + ty * 8 + i;
        if (row >= N_NODES) continue;
#pragma unroll
        for (int j = 0; j < 4; j++) {
            float lo, hi;
            asm("mov.b64 {%0,%1}, %2;" : "=f"(lo), "=f"(hi) : "l"(acc[i][j]));
            int c = tx * 8 + 2 * j;   // 0..126; a thread's 8 cols never straddle 64
            if (c < F_OUT)
                *(float2*)&g_p[row * F_OUT + c] = make_float2(lo, hi);
            else
                *(float2*)&r_out[row * F_OUT + (c - F_OUT)] = make_float2(lo, hi);
        }
    }
}

// ---------------- layer-2 scatter: agg2[dst] += p[src] ----------------------
__global__ void scatter2_kernel(const int* __restrict__ ei) {
    int t = blockIdx.x * blockDim.x + threadIdx.x;
    int e = t >> 4;
    int c = t & 15;
    if (e >= N_EDGES) return;
    int src = ei[e];
    int dst = ei[N_EDGES + e];
    float4 v = ((const float4*)g_p)[src * (F_OUT / 4) + c];
    red_add_v4(g_agg2 + dst * F_OUT + c * 4, v);
}

// ---------------- finalize: out = sigmoid(agg2/deg + r + b2) ----------------
__global__ void finalize_kernel(const float* __restrict__ b2, float* __restrict__ out) {
    int idx = blockIdx.x * blockDim.x + threadIdx.x;
    if (idx >= N_NODES * F_OUT) return;
    int n = idx >> 6;
    int j = idx & 63;
    float inv = 1.0f / fmaxf(g_deg[n], 1.0f);
    float z = g_agg2[idx] * inv + out[idx] + b2[j];
    out[idx] = 1.0f / (1.0f + expf(-z));
}

// ---------------- launch -----------------------------------------------------
extern "C" void kernel_launch(void* const* d_in, const int* in_sizes, int n_in,
                              void* d_out, int out_size) {
    const float* x   = (const float*)d_in[0];
    const int*   ei  = (const int*)d_in[1];
    const float* Wl1 = (const float*)d_in[2];
    const float* Wr1 = (const float*)d_in[3];
    const float* b1  = (const float*)d_in[4];
    const float* Wl2 = (const float*)d_in[5];
    const float* Wr2 = (const float*)d_in[6];
    const float* b2  = (const float*)d_in[7];
    float* out = (float*)d_out;

    {
        int tot = N_NODES * F_IN / 4 + N_NODES * F_OUT / 4 + N_NODES / 4;
        zero_kernel<<<(tot + 255) / 256, 256>>>();
    }
    scatter1_kernel<<<(N_EDGES * 32) / 256, 256>>>(x, ei);
    {
        dim3 g((N_NODES + BM - 1) / BM, F_HID / BN);
        gemm1_kernel<<<g, 256>>>(x, Wl1, Wr1, b1);
    }
    {
        dim3 g((N_NODES + BM - 1) / BM, 1);
        gemm2_kernel<<<g, 256>>>(Wl2, Wr2, out);
    }
    scatter2_kernel<<<(N_EDGES * 16) / 256, 256>>>(ei);
    finalize_kernel<<<(N_NODES * F_OUT + 255) / 256, 256>>>(b2, out);
}

// round 8
// speedup vs baseline: 1.3847x; 1.1313x over previous
#include <cuda_runtime.h>

#define N_NODES 50000
#define N_EDGES 800000
#define F_IN 128
#define F_HID 256
#define F_OUT 64

// ---------------- scratch (static device allocations; no cudaMalloc) -------
__device__ __align__(16) float g_agg1[N_NODES * F_IN];    // 25.6 MB (means)
__device__ __align__(16) float g_h[N_NODES * F_HID];      // 51.2 MB
__device__ __align__(16) float g_p[N_NODES * F_OUT];      // 12.8 MB
__device__ int g_cnt[N_NODES];
__device__ int g_cursor[N_NODES];
__device__ int g_row_ptr[N_NODES + 1];
__device__ int g_csr_src[N_EDGES];

// ---------------- CSR build --------------------------------------------------
__global__ void zero_cnt_kernel() {
    int i = blockIdx.x * blockDim.x + threadIdx.x;
    if (i < N_NODES) g_cnt[i] = 0;
}

__global__ void count_kernel(const int* __restrict__ ei) {
    int e = blockIdx.x * blockDim.x + threadIdx.x;
    if (e >= N_EDGES) return;
    atomicAdd(&g_cnt[ei[N_EDGES + e]], 1);
}

// single-block exclusive scan over g_cnt -> g_row_ptr / g_cursor
__global__ __launch_bounds__(1024) void scan_kernel() {
    __shared__ int ssum[1024];
    const int t = threadIdx.x;
    const int CH = (N_NODES + 1023) / 1024;   // 49
    int beg = t * CH;
    int end = min(beg + CH, N_NODES);
    int s = 0;
    for (int i = beg; i < end; i++) s += g_cnt[i];
    ssum[t] = s;
    __syncthreads();
    for (int off = 1; off < 1024; off <<= 1) {
        int tmp = (t >= off) ? ssum[t - off] : 0;
        __syncthreads();
        ssum[t] += tmp;
        __syncthreads();
    }
    int base = ssum[t] - s;   // exclusive prefix of this thread's chunk
    for (int i = beg; i < end; i++) {
        int c = g_cnt[i];
        g_row_ptr[i] = base;
        g_cursor[i] = base;
        base += c;
    }
    if (t == 1023) g_row_ptr[N_NODES] = base;
}

__global__ void place_kernel(const int* __restrict__ ei) {
    int e = blockIdx.x * blockDim.x + threadIdx.x;
    if (e >= N_EDGES) return;
    int src = ei[e];
    int dst = ei[N_EDGES + e];
    int pos = atomicAdd(&g_cursor[dst], 1);
    g_csr_src[pos] = src;
}

// ---------------- layer-1 gather: agg1[n] = mean_{s in N(n)} x[s] -----------
// one warp per node, lane = one float4 of the 128-float row
__global__ __launch_bounds__(256) void gather1_kernel(const float* __restrict__ x) {
    int w = (blockIdx.x * blockDim.x + threadIdx.x) >> 5;
    int lane = threadIdx.x & 31;
    if (w >= N_NODES) return;
    int beg = g_row_ptr[w], end = g_row_ptr[w + 1];
    float4 acc = make_float4(0.f, 0.f, 0.f, 0.f);
    int i = beg;
    for (; i + 1 < end; i += 2) {
        int s0 = __ldg(&g_csr_src[i]);
        int s1 = __ldg(&g_csr_src[i + 1]);
        float4 v0 = __ldg(&((const float4*)x)[s0 * 32 + lane]);
        float4 v1 = __ldg(&((const float4*)x)[s1 * 32 + lane]);
        acc.x += v0.x + v1.x; acc.y += v0.y + v1.y;
        acc.z += v0.z + v1.z; acc.w += v0.w + v1.w;
    }
    if (i < end) {
        int s0 = __ldg(&g_csr_src[i]);
        float4 v0 = __ldg(&((const float4*)x)[s0 * 32 + lane]);
        acc.x += v0.x; acc.y += v0.y; acc.z += v0.z; acc.w += v0.w;
    }
    float inv = (end > beg) ? 1.0f / (float)(end - beg) : 0.f;
    acc.x *= inv; acc.y *= inv; acc.z *= inv; acc.w *= inv;
    ((float4*)g_agg1)[w * 32 + lane] = acc;
}

// ---------------- GEMM tiles ------------------------------------------------
// BM=128, BN=128, BK=16, 256 threads, 8x8 thread tile (4 f32x2 pairs),
// double-buffered smem + register prefetch, one __syncthreads per K-tile.
#define BM 128
#define BN 128
#define BK 16
#define AS_LD (BM + 4)

#define COMPUTE_TILE(buf)                                                       \
    do {                                                                        \
        _Pragma("unroll")                                                       \
        for (int kk = 0; kk < BK; kk++) {                                       \
            float4 a0 = *(const float4*)&As[buf][kk][ty * 8];                   \
            float4 a1 = *(const float4*)&As[buf][kk][ty * 8 + 4];               \
            ulonglong2 bq0 = *(const ulonglong2*)&Bs[buf][kk][tx * 8];          \
            ulonglong2 bq1 = *(const ulonglong2*)&Bs[buf][kk][tx * 8 + 4];      \
            unsigned long long bp[4] = {bq0.x, bq0.y, bq1.x, bq1.y};            \
            float a[8] = {a0.x, a0.y, a0.z, a0.w, a1.x, a1.y, a1.z, a1.w};      \
            _Pragma("unroll")                                                   \
            for (int i = 0; i < 8; i++) {                                       \
                unsigned long long aa;                                          \
                asm("mov.b64 %0, {%1,%1};" : "=l"(aa) : "f"(a[i]));             \
                _Pragma("unroll")                                               \
                for (int j = 0; j < 4; j++)                                     \
                    asm("fma.rn.f32x2 %0, %1, %2, %0;"                          \
                        : "+l"(acc[i][j]) : "l"(aa), "l"(bp[j]));               \
            }                                                                   \
        }                                                                       \
    } while (0)

#define STORE_TILE(buf, pa0v, pa1v, pb0v, pb1v)                                 \
    do {                                                                        \
        As[buf][ak][am0] = pa0v.x; As[buf][ak + 1][am0] = pa0v.y;               \
        As[buf][ak + 2][am0] = pa0v.z; As[buf][ak + 3][am0] = pa0v.w;           \
        As[buf][ak][am0 + 64] = pa1v.x; As[buf][ak + 1][am0 + 64] = pa1v.y;     \
        As[buf][ak + 2][am0 + 64] = pa1v.z; As[buf][ak + 3][am0 + 64] = pa1v.w; \
        *(float4*)&Bs[buf][bk0][bc0] = pb0v;                                    \
        *(float4*)&Bs[buf][bk1][bc1] = pb1v;                                    \
    } while (0)

// GEMM 1: h = relu([agg1 | x] @ [W_l1 ; W_r1] + b1), K = 256
__global__ __launch_bounds__(256, 2) void gemm1_kernel(
    const float* __restrict__ x, const float* __restrict__ Wl,
    const float* __restrict__ Wr, const float* __restrict__ bias)
{
    __shared__ float As[2][BK][AS_LD];
    __shared__ float Bs[2][BK][BN];
    const int tid = threadIdx.x;
    const int row_base = blockIdx.x * BM;
    const int col_base = blockIdx.y * BN;
    const int tx = tid & 15;
    const int ty = tid >> 4;

    unsigned long long acc[8][4];
#pragma unroll
    for (int i = 0; i < 8; i++)
#pragma unroll
        for (int j = 0; j < 4; j++) acc[i][j] = 0ULL;

    const int ak = (tid & 3) * 4;
    const int am0 = tid >> 2;
    const int arow0 = row_base + am0;
    const int arow1 = arow0 + 64;

#define G1_LOAD_A(dst0, dst1, k0v)                                              \
    do {                                                                        \
        int gk = (k0v) + ak;                                                    \
        dst0 = make_float4(0.f, 0.f, 0.f, 0.f);                                 \
        dst1 = make_float4(0.f, 0.f, 0.f, 0.f);                                 \
        if (gk < F_IN) {                                                        \
            if (arow0 < N_NODES) dst0 = *(const float4*)(g_agg1 + arow0 * F_IN + gk); \
            if (arow1 < N_NODES) dst1 = *(const float4*)(g_agg1 + arow1 * F_IN + gk); \
        } else {                                                                \
            if (arow0 < N_NODES) dst0 = *(const float4*)(x + arow0 * F_IN + gk - F_IN); \
            if (arow1 < N_NODES) dst1 = *(const float4*)(x + arow1 * F_IN + gk - F_IN); \
        }                                                                       \
    } while (0)

    const int bk0 = tid >> 5, bc0 = (tid & 31) * 4;
    const int bk1 = (tid + 256) >> 5, bc1 = (tid & 31) * 4;
#define G1_LOAD_B(dst0, dst1, k0v)                                              \
    do {                                                                        \
        int gk0 = (k0v) + bk0, gk1 = (k0v) + bk1;                               \
        const float* s0 = (gk0 < F_IN) ? (Wl + gk0 * F_HID + col_base + bc0)    \
                                       : (Wr + (gk0 - F_IN) * F_HID + col_base + bc0); \
        const float* s1 = (gk1 < F_IN) ? (Wl + gk1 * F_HID + col_base + bc1)    \
                                       : (Wr + (gk1 - F_IN) * F_HID + col_base + bc1); \
        dst0 = *(const float4*)s0;                                              \
        dst1 = *(const float4*)s1;                                              \
    } while (0)

    {
        float4 pa0, pa1, pb0, pb1;
        G1_LOAD_A(pa0, pa1, 0);
        G1_LOAD_B(pb0, pb1, 0);
        STORE_TILE(0, pa0, pa1, pb0, pb1);
    }
    __syncthreads();

    const int NT = (2 * F_IN) / BK;   // 16
    for (int c = 0; c < NT; c++) {
        float4 pa0, pa1, pb0, pb1;
        if (c + 1 < NT) {
            G1_LOAD_A(pa0, pa1, (c + 1) * BK);
            G1_LOAD_B(pb0, pb1, (c + 1) * BK);
        }
        COMPUTE_TILE(c & 1);
        if (c + 1 < NT) STORE_TILE((c + 1) & 1, pa0, pa1, pb0, pb1);
        __syncthreads();
    }

#pragma unroll
    for (int i = 0; i < 8; i++) {
        int row = row_base + ty * 8 + i;
        if (row >= N_NODES) continue;
#pragma unroll
        for (int j = 0; j < 4; j++) {
            float lo, hi;
            asm("mov.b64 {%0,%1}, %2;" : "=f"(lo), "=f"(hi) : "l"(acc[i][j]));
            int c = col_base + tx * 8 + 2 * j;
            lo = fmaxf(lo + bias[c], 0.f);
            hi = fmaxf(hi + bias[c + 1], 0.f);
            *(float2*)&g_h[row * F_HID + c] = make_float2(lo, hi);
        }
    }
}

// GEMM 2: [p | r] = h @ [W_l2 | W_r2], K = 256
__global__ __launch_bounds__(256, 2) void gemm2_kernel(
    const float* __restrict__ Wl, const float* __restrict__ Wr,
    float* __restrict__ r_out)
{
    __shared__ float As[2][BK][AS_LD];
    __shared__ float Bs[2][BK][BN];
    const int tid = threadIdx.x;
    const int row_base = blockIdx.x * BM;
    const int tx = tid & 15;
    const int ty = tid >> 4;

    unsigned long long acc[8][4];
#pragma unroll
    for (int i = 0; i < 8; i++)
#pragma unroll
        for (int j = 0; j < 4; j++) acc[i][j] = 0ULL;

    const int ak = (tid & 3) * 4;
    const int am0 = tid >> 2;
    const int arow0 = row_base + am0;
    const int arow1 = arow0 + 64;

#define G2_LOAD_A(dst0, dst1, k0v)                                              \
    do {                                                                        \
        int gk = (k0v) + ak;                                                    \
        dst0 = make_float4(0.f, 0.f, 0.f, 0.f);                                 \
        dst1 = make_float4(0.f, 0.f, 0.f, 0.f);                                 \
        if (arow0 < N_NODES) dst0 = *(const float4*)(g_h + arow0 * F_HID + gk); \
        if (arow1 < N_NODES) dst1 = *(const float4*)(g_h + arow1 * F_HID + gk); \
    } while (0)

    const int bk0 = tid >> 5, bc0 = (tid & 31) * 4;
    const int bk1 = (tid + 256) >> 5, bc1 = (tid & 31) * 4;
#define G2_LOAD_B(dst0, dst1, k0v)                                              \
    do {                                                                        \
        int gk0 = (k0v) + bk0, gk1 = (k0v) + bk1;                               \
        const float* s0 = (bc0 < F_OUT) ? (Wl + gk0 * F_OUT + bc0)              \
                                        : (Wr + gk0 * F_OUT + (bc0 - F_OUT));   \
        const float* s1 = (bc1 < F_OUT) ? (Wl + gk1 * F_OUT + bc1)              \
                                        : (Wr + gk1 * F_OUT + (bc1 - F_OUT));   \
        dst0 = *(const float4*)s0;                                              \
        dst1 = *(const float4*)s1;                                              \
    } while (0)

    {
        float4 pa0, pa1, pb0, pb1;
        G2_LOAD_A(pa0, pa1, 0);
        G2_LOAD_B(pb0, pb1, 0);
        STORE_TILE(0, pa0, pa1, pb0, pb1);
    }
    __syncthreads();

    const int NT = F_HID / BK;   // 16
    for (int c = 0; c < NT; c++) {
        float4 pa0, pa1, pb0, pb1;
        if (c + 1 < NT) {
            G2_LOAD_A(pa0, pa1, (c + 1) * BK);
            G2_LOAD_B(pb0, pb1, (c + 1) * BK);
        }
        COMPUTE_TILE(c & 1);
        if (c + 1 < NT) STORE_TILE((c + 1) & 1, pa0, pa1, pb0, pb1);
        __syncthreads();
    }

#pragma unroll
    for (int i = 0; i < 8; i++) {
        int row = row_base + ty * 8 + i;
        if (row >= N_NODES) continue;
#pragma unroll
        for (int j = 0; j < 4; j++) {
            float lo, hi;
            asm("mov.b64 {%0,%1}, %2;" : "=f"(lo), "=f"(hi) : "l"(acc[i][j]));
            int c = tx * 8 + 2 * j;   // 0..126; never straddles 64
            if (c < F_OUT)
                *(float2*)&g_p[row * F_OUT + c] = make_float2(lo, hi);
            else
                *(float2*)&r_out[row * F_OUT + (c - F_OUT)] = make_float2(lo, hi);
        }
    }
}

// ------- layer-2 gather + finalize: out = sigmoid(mean(p[N(n)]) + r + b2) ---
// one warp per node, lane = one float2 of the 64-float row
__global__ __launch_bounds__(256) void gather2_fin_kernel(
    const float* __restrict__ b2, float* __restrict__ out)
{
    int w = (blockIdx.x * blockDim.x + threadIdx.x) >> 5;
    int lane = threadIdx.x & 31;
    if (w >= N_NODES) return;
    int beg = g_row_ptr[w], end = g_row_ptr[w + 1];
    float2 acc = make_float2(0.f, 0.f);
    int i = beg;
    for (; i + 1 < end; i += 2) {
        int s0 = __ldg(&g_csr_src[i]);
        int s1 = __ldg(&g_csr_src[i + 1]);
        float2 v0 = __ldg(&((const float2*)g_p)[s0 * 32 + lane]);
        float2 v1 = __ldg(&((const float2*)g_p)[s1 * 32 + lane]);
        acc.x += v0.x + v1.x; acc.y += v0.y + v1.y;
    }
    if (i < end) {
        int s0 = __ldg(&g_csr_src[i]);
        float2 v0 = __ldg(&((const float2*)g_p)[s0 * 32 + lane]);
        acc.x += v0.x; acc.y += v0.y;
    }
    float inv = (end > beg) ? 1.0f / (float)(end - beg) : 0.f;
    float2 r = ((const float2*)out)[w * 32 + lane];
    float zx = acc.x * inv + r.x + b2[lane * 2];
    float zy = acc.y * inv + r.y + b2[lane * 2 + 1];
    float2 o;
    o.x = 1.0f / (1.0f + expf(-zx));
    o.y = 1.0f / (1.0f + expf(-zy));
    ((float2*)out)[w * 32 + lane] = o;
}

// ---------------- launch -----------------------------------------------------
extern "C" void kernel_launch(void* const* d_in, const int* in_sizes, int n_in,
                              void* d_out, int out_size) {
    const float* x   = (const float*)d_in[0];
    const int*   ei  = (const int*)d_in[1];
    const float* Wl1 = (const float*)d_in[2];
    const float* Wr1 = (const float*)d_in[3];
    const float* b1  = (const float*)d_in[4];
    const float* Wl2 = (const float*)d_in[5];
    const float* Wr2 = (const float*)d_in[6];
    const float* b2  = (const float*)d_in[7];
    float* out = (float*)d_out;

    zero_cnt_kernel<<<(N_NODES + 255) / 256, 256>>>();
    count_kernel<<<(N_EDGES + 255) / 256, 256>>>(ei);
    scan_kernel<<<1, 1024>>>();
    place_kernel<<<(N_EDGES + 255) / 256, 256>>>(ei);
    gather1_kernel<<<(N_NODES * 32 + 255) / 256, 256>>>(x);
    {
        dim3 g((N_NODES + BM - 1) / BM, F_HID / BN);
        gemm1_kernel<<<g, 256>>>(x, Wl1, Wr1, b1);
    }
    {
        dim3 g((N_NODES + BM - 1) / BM, 1);
        gemm2_kernel<<<g, 256>>>(Wl2, Wr2, out);
    }
    gather2_fin_kernel<<<(N_NODES * 32 + 255) / 256, 256>>>(b2, out);
}

// round 16
// speedup vs baseline: 1.9462x; 1.4055x over previous
#include <cuda_runtime.h>
#include <cuda_bf16.h>
#include <cstdint>

#define N_NODES 50000
#define N_EDGES 800000
#define F_IN 128
#define F_HID 256
#define F_OUT 64

typedef unsigned short u16;
typedef unsigned int u32;

// ---------------- scratch ----------------------------------------------------
__device__ __align__(16) u16 g_A1h[N_NODES * 256];   // [m][k]: cols 0-127 mean, 128-255 x (bf16 hi)
__device__ __align__(16) u16 g_A1l[N_NODES * 256];   // bf16 lo
__device__ __align__(16) u16 g_A2h[N_NODES * 256];   // h split hi
__device__ __align__(16) u16 g_A2l[N_NODES * 256];   // h split lo
__device__ __align__(16) u16 g_B1h[256 * 256];       // [n][k] = [W_l1;W_r1]^T hi
__device__ __align__(16) u16 g_B1l[256 * 256];
__device__ __align__(16) u16 g_B2h[128 * 256];       // [n][k] = [W_l2|W_r2]^T hi
__device__ __align__(16) u16 g_B2l[128 * 256];
__device__ __align__(16) float g_p[N_NODES * F_OUT]; // h @ W_l2
__device__ int g_cnt[N_NODES];
__device__ int g_cursor[N_NODES];
__device__ int g_row_ptr[N_NODES + 1];
__device__ int g_csr_src[N_EDGES];

// ---------------- helpers ----------------------------------------------------
__device__ __forceinline__ u32 smem_u32(const void* p) {
    u32 a;
    asm("{ .reg .u64 t; cvta.to.shared.u64 t, %1; cvt.u32.u64 %0, t; }" : "=r"(a) : "l"(p));
    return a;
}
__device__ __forceinline__ u32 lds32(u32 a) {
    u32 v;
    asm volatile("ld.shared.b32 %0, [%1];" : "=r"(v) : "r"(a));
    return v;
}
#define CP16(dst, src, sz)                                                     \
    asm volatile("cp.async.cg.shared.global [%0], [%1], 16, %2;"               \
                 :: "r"(dst), "l"(src), "r"(sz) : "memory")
#define CP_COMMIT() asm volatile("cp.async.commit_group;" ::: "memory")
#define CP_WAIT1()  asm volatile("cp.async.wait_group 1;" ::: "memory")

#define MMA_BF16(d, a, b0v, b1v)                                               \
    asm volatile("mma.sync.aligned.m16n8k16.row.col.f32.bf16.bf16.f32 "        \
                 "{%0,%1,%2,%3}, {%4,%5,%6,%7}, {%8,%9}, {%0,%1,%2,%3};"       \
                 : "+f"((d)[0]), "+f"((d)[1]), "+f"((d)[2]), "+f"((d)[3])      \
                 : "r"((a)[0]), "r"((a)[1]), "r"((a)[2]), "r"((a)[3]),         \
                   "r"(b0v), "r"(b1v))

__device__ __forceinline__ void split_bf16(float f, u16& hi, u16& lo) {
    __nv_bfloat16 h = __float2bfloat16(f);
    float r = f - __bfloat162float(h);
    __nv_bfloat16 l = __float2bfloat16(r);
    hi = __bfloat16_as_ushort(h);
    lo = __bfloat16_as_ushort(l);
}
__device__ __forceinline__ u32 pack_split_hi(float v0, float v1, u32& lopack) {
    u16 h0, l0, h1, l1;
    split_bf16(v0, h0, l0);
    split_bf16(v1, h1, l1);
    lopack = (u32)l0 | ((u32)l1 << 16);
    return (u32)h0 | ((u32)h1 << 16);
}

// ---------------- CSR build --------------------------------------------------
__global__ void zero_cnt_kernel() {
    int i = blockIdx.x * blockDim.x + threadIdx.x;
    if (i < N_NODES) g_cnt[i] = 0;
}
__global__ void count_kernel(const int* __restrict__ ei) {
    int e = blockIdx.x * blockDim.x + threadIdx.x;
    if (e >= N_EDGES) return;
    atomicAdd(&g_cnt[ei[N_EDGES + e]], 1);
}
__global__ __launch_bounds__(1024) void scan_kernel() {
    __shared__ int ssum[1024];
    const int t = threadIdx.x;
    const int CH = (N_NODES + 1023) / 1024;
    int beg = t * CH;
    int end = min(beg + CH, N_NODES);
    int s = 0;
    for (int i = beg; i < end; i++) s += g_cnt[i];
    ssum[t] = s;
    __syncthreads();
    for (int off = 1; off < 1024; off <<= 1) {
        int tmp = (t >= off) ? ssum[t - off] : 0;
        __syncthreads();
        ssum[t] += tmp;
        __syncthreads();
    }
    int base = ssum[t] - s;
    for (int i = beg; i < end; i++) {
        int c = g_cnt[i];
        g_row_ptr[i] = base;
        g_cursor[i] = base;
        base += c;
    }
    if (t == 1023) g_row_ptr[N_NODES] = base;
}
__global__ void place_kernel(const int* __restrict__ ei) {
    int e = blockIdx.x * blockDim.x + threadIdx.x;
    if (e >= N_EDGES) return;
    int src = ei[e];
    int dst = ei[N_EDGES + e];
    int pos = atomicAdd(&g_cursor[dst], 1);
    g_csr_src[pos] = src;
}

// ---------------- layer-1 gather -> bf16 split mean -------------------------
// one warp per node; lane owns 4 cols
__global__ __launch_bounds__(256) void gather1_kernel(const float* __restrict__ x) {
    int w = (blockIdx.x * blockDim.x + threadIdx.x) >> 5;
    int lane = threadIdx.x & 31;
    if (w >= N_NODES) return;
    int beg = g_row_ptr[w], end = g_row_ptr[w + 1];
    float4 acc = make_float4(0.f, 0.f, 0.f, 0.f);
    int i = beg;
    for (; i + 1 < end; i += 2) {
        int s0 = __ldg(&g_csr_src[i]);
        int s1 = __ldg(&g_csr_src[i + 1]);
        float4 v0 = __ldg(&((const float4*)x)[s0 * 32 + lane]);
        float4 v1 = __ldg(&((const float4*)x)[s1 * 32 + lane]);
        acc.x += v0.x + v1.x; acc.y += v0.y + v1.y;
        acc.z += v0.z + v1.z; acc.w += v0.w + v1.w;
    }
    if (i < end) {
        int s0 = __ldg(&g_csr_src[i]);
        float4 v0 = __ldg(&((const float4*)x)[s0 * 32 + lane]);
        acc.x += v0.x; acc.y += v0.y; acc.z += v0.z; acc.w += v0.w;
    }
    float inv = (end > beg) ? 1.0f / (float)(end - beg) : 0.f;
    acc.x *= inv; acc.y *= inv; acc.z *= inv; acc.w *= inv;
    u32 l0, l1;
    u32 h0 = pack_split_hi(acc.x, acc.y, l0);
    u32 h1 = pack_split_hi(acc.z, acc.w, l1);
    int o = w * 256 + lane * 4;
    *(uint2*)&g_A1h[o] = make_uint2(h0, h1);
    *(uint2*)&g_A1l[o] = make_uint2(l0, l1);
}

// ---------------- x split into A1 cols 128-255 -------------------------------
__global__ void xsplit_kernel(const float* __restrict__ x) {
    int idx = blockIdx.x * blockDim.x + threadIdx.x;   // one float4 each
    if (idx >= N_NODES * 32) return;
    int m = idx >> 5, c = idx & 31;
    float4 v = __ldg(&((const float4*)x)[idx]);
    u32 l0, l1;
    u32 h0 = pack_split_hi(v.x, v.y, l0);
    u32 h1 = pack_split_hi(v.z, v.w, l1);
    int o = m * 256 + 128 + c * 4;
    *(uint2*)&g_A1h[o] = make_uint2(h0, h1);
    *(uint2*)&g_A1l[o] = make_uint2(l0, l1);
}

// ---------------- weight prep: transpose + split ----------------------------
__global__ void prep_B_kernel(const float* __restrict__ Wl1, const float* __restrict__ Wr1,
                              const float* __restrict__ Wl2, const float* __restrict__ Wr2) {
    int idx = blockIdx.x * blockDim.x + threadIdx.x;
    if (idx < 256 * 256) {
        int n = idx >> 8, k = idx & 255;
        float v = (k < 128) ? Wl1[k * F_HID + n] : Wr1[(k - 128) * F_HID + n];
        u16 hi, lo;
        split_bf16(v, hi, lo);
        g_B1h[n * 256 + k] = hi;
        g_B1l[n * 256 + k] = lo;
    } else if (idx < 256 * 256 + 128 * 256) {
        int r = idx - 256 * 256;
        int n = r >> 8, k = r & 255;
        float v = (n < 64) ? Wl2[k * F_OUT + n] : Wr2[k * F_OUT + (n - 64)];
        u16 hi, lo;
        split_bf16(v, hi, lo);
        g_B2h[n * 256 + k] = hi;
        g_B2l[n * 256 + k] = lo;
    }
}

// ---------------- bf16 mma GEMM core ----------------------------------------
// CTA: 128m x 128n, 8 warps (4m x 2n), warp tile 32m x 64n.
// K = 256 in 8 chunks of 32. smem row = 64B data + 16B pad (80B stride).
// Buffer layout (per buf, 40960B): Ah@0, Al@10240, Bh@20480, Bl@30720.
#define ROWB 80
#define REG 10240
#define BUFB 40960
#define SMEM_TOT (2 * BUFB)

__device__ __forceinline__ void load_chunk(
    u32 sb_buf, int c, int row_base, int bbase,
    const u16* Ah, const u16* Al, const u16* Bh, const u16* Bl, int tid)
{
#pragma unroll
    for (int i = 0; i < 2; i++) {
        int t2 = tid * 2 + i;
        int row = t2 >> 2, q = t2 & 3;
        int gr = row_base + row;
        int szA = (gr < N_NODES) ? 16 : 0;
        int grc = (gr < N_NODES) ? gr : 0;
        u32 d = sb_buf + row * ROWB + q * 16;
        CP16(d,           Ah + grc * 256 + c * 32 + q * 8, szA);
        CP16(d + REG,     Al + grc * 256 + c * 32 + q * 8, szA);
        int bn = bbase + row;
        CP16(d + 2 * REG, Bh + bn * 256 + c * 32 + q * 8, 16);
        CP16(d + 3 * REG, Bl + bn * 256 + c * 32 + q * 8, 16);
    }
}

__device__ __forceinline__ void compute_chunk(
    u32 sb_buf, float (&acc)[2][8][4], int lane, int warp_m, int warp_n)
{
#pragma unroll
    for (int ks = 0; ks < 2; ks++) {
        int kb = ks * 32;   // byte offset of k-step within row
        u32 ah[2][4], al[2][4];
#pragma unroll
        for (int mt = 0; mt < 2; mt++) {
            u32 ab = sb_buf + (warp_m * 32 + mt * 16 + (lane >> 2)) * ROWB + kb + (lane & 3) * 4;
            ah[mt][0] = lds32(ab);
            ah[mt][1] = lds32(ab + 8 * ROWB);
            ah[mt][2] = lds32(ab + 16);
            ah[mt][3] = lds32(ab + 8 * ROWB + 16);
            al[mt][0] = lds32(ab + REG);
            al[mt][1] = lds32(ab + REG + 8 * ROWB);
            al[mt][2] = lds32(ab + REG + 16);
            al[mt][3] = lds32(ab + REG + 8 * ROWB + 16);
        }
#pragma unroll
        for (int nt = 0; nt < 8; nt++) {
            u32 bb = sb_buf + 2 * REG + (warp_n * 64 + nt * 8 + (lane >> 2)) * ROWB + kb + (lane & 3) * 4;
            u32 bh0 = lds32(bb), bh1 = lds32(bb + 16);
            u32 bl0 = lds32(bb + REG), bl1 = lds32(bb + REG + 16);
#pragma unroll
            for (int mt = 0; mt < 2; mt++) {
                MMA_BF16(acc[mt][nt], ah[mt], bh0, bh1);
                MMA_BF16(acc[mt][nt], ah[mt], bl0, bl1);
                MMA_BF16(acc[mt][nt], al[mt], bh0, bh1);
            }
        }
    }
}

#define GEMM_PIPELINE(AH, AL, BH, BL, BBASE)                                   \
    u32 sb = smem_u32(sm);                                                     \
    const int tid = threadIdx.x;                                               \
    const int lane = tid & 31, wid = tid >> 5;                                 \
    const int warp_m = wid & 3, warp_n = wid >> 2;                             \
    const int row_base = blockIdx.x * 128;                                     \
    float acc[2][8][4];                                                        \
    _Pragma("unroll") for (int a_ = 0; a_ < 2; a_++)                           \
    _Pragma("unroll") for (int b_ = 0; b_ < 8; b_++)                           \
    _Pragma("unroll") for (int c_ = 0; c_ < 4; c_++) acc[a_][b_][c_] = 0.f;    \
    load_chunk(sb, 0, row_base, BBASE, AH, AL, BH, BL, tid);                   \
    CP_COMMIT();                                                               \
    load_chunk(sb + BUFB, 1, row_base, BBASE, AH, AL, BH, BL, tid);            \
    CP_COMMIT();                                                               \
    for (int c = 0; c < 8; c++) {                                              \
        CP_WAIT1();                                                            \
        __syncthreads();                                                       \
        compute_chunk(sb + (c & 1) * BUFB, acc, lane, warp_m, warp_n);         \
        __syncthreads();                                                       \
        if (c < 6)                                                             \
            load_chunk(sb + (c & 1) * BUFB, c + 2, row_base, BBASE, AH, AL, BH, BL, tid); \
        CP_COMMIT();                                                           \
    }

// GEMM 1: h = relu(A1 @ B1^T + b1) -> A2 (bf16 split). grid (391, 2).
__global__ __launch_bounds__(256, 2) void gemm1_mma(const float* __restrict__ bias) {
    extern __shared__ char sm[];
    const int cb = blockIdx.y * 128;
    GEMM_PIPELINE(g_A1h, g_A1l, g_B1h, g_B1l, cb)
    // epilogue
#pragma unroll
    for (int mt = 0; mt < 2; mt++) {
#pragma unroll
        for (int nt = 0; nt < 8; nt++) {
            int col = cb + warp_n * 64 + nt * 8 + (lane & 3) * 2;
            float b0 = __ldg(bias + col), b1v = __ldg(bias + col + 1);
            int r0 = row_base + warp_m * 32 + mt * 16 + (lane >> 2);
            if (r0 < N_NODES) {
                float v0 = fmaxf(acc[mt][nt][0] + b0, 0.f);
                float v1 = fmaxf(acc[mt][nt][1] + b1v, 0.f);
                u32 lp, hp = pack_split_hi(v0, v1, lp);
                *(u32*)&g_A2h[r0 * 256 + col] = hp;
                *(u32*)&g_A2l[r0 * 256 + col] = lp;
            }
            int r1 = r0 + 8;
            if (r1 < N_NODES) {
                float v0 = fmaxf(acc[mt][nt][2] + b0, 0.f);
                float v1 = fmaxf(acc[mt][nt][3] + b1v, 0.f);
                u32 lp, hp = pack_split_hi(v0, v1, lp);
                *(u32*)&g_A2h[r1 * 256 + col] = hp;
                *(u32*)&g_A2l[r1 * 256 + col] = lp;
            }
        }
    }
}

// GEMM 2: [p | r] = A2 @ B2^T; p -> g_p, r -> out (pre-sigmoid). grid (391, 1).
__global__ __launch_bounds__(256, 2) void gemm2_mma(float* __restrict__ r_out) {
    extern __shared__ char sm[];
    GEMM_PIPELINE(g_A2h, g_A2l, g_B2h, g_B2l, 0)
#pragma unroll
    for (int mt = 0; mt < 2; mt++) {
#pragma unroll
        for (int nt = 0; nt < 8; nt++) {
            int col = warp_n * 64 + nt * 8 + (lane & 3) * 2;
            int r0 = row_base + warp_m * 32 + mt * 16 + (lane >> 2);
            if (r0 < N_NODES) {
                float2 v = make_float2(acc[mt][nt][0], acc[mt][nt][1]);
                if (col < F_OUT) *(float2*)&g_p[r0 * F_OUT + col] = v;
                else             *(float2*)&r_out[r0 * F_OUT + col - F_OUT] = v;
            }
            int r1 = r0 + 8;
            if (r1 < N_NODES) {
                float2 v = make_float2(acc[mt][nt][2], acc[mt][nt][3]);
                if (col < F_OUT) *(float2*)&g_p[r1 * F_OUT + col] = v;
                else             *(float2*)&r_out[r1 * F_OUT + col - F_OUT] = v;
            }
        }
    }
}

// ------- layer-2 gather + finalize: out = sigmoid(mean(p[N(n)]) + r + b2) ---
__global__ __launch_bounds__(256) void gather2_fin_kernel(
    const float* __restrict__ b2, float* __restrict__ out)
{
    int w = (blockIdx.x * blockDim.x + threadIdx.x) >> 5;
    int lane = threadIdx.x & 31;
    if (w >= N_NODES) return;
    int beg = g_row_ptr[w], end = g_row_ptr[w + 1];
    float2 acc = make_float2(0.f, 0.f);
    int i = beg;
    for (; i + 1 < end; i += 2) {
        int s0 = __ldg(&g_csr_src[i]);
        int s1 = __ldg(&g_csr_src[i + 1]);
        float2 v0 = __ldg(&((const float2*)g_p)[s0 * 32 + lane]);
        float2 v1 = __ldg(&((const float2*)g_p)[s1 * 32 + lane]);
        acc.x += v0.x + v1.x; acc.y += v0.y + v1.y;
    }
    if (i < end) {
        int s0 = __ldg(&g_csr_src[i]);
        float2 v0 = __ldg(&((const float2*)g_p)[s0 * 32 + lane]);
        acc.x += v0.x; acc.y += v0.y;
    }
    float inv = (end > beg) ? 1.0f / (float)(end - beg) : 0.f;
    float2 r = ((const float2*)out)[w * 32 + lane];
    float zx = acc.x * inv + r.x + b2[lane * 2];
    float zy = acc.y * inv + r.y + b2[lane * 2 + 1];
    float2 o;
    o.x = 1.0f / (1.0f + expf(-zx));
    o.y = 1.0f / (1.0f + expf(-zy));
    ((float2*)out)[w * 32 + lane] = o;
}

// ---------------- launch -----------------------------------------------------
extern "C" void kernel_launch(void* const* d_in, const int* in_sizes, int n_in,
                              void* d_out, int out_size) {
    const float* x   = (const float*)d_in[0];
    const int*   ei  = (const int*)d_in[1];
    const float* Wl1 = (const float*)d_in[2];
    const float* Wr1 = (const float*)d_in[3];
    const float* b1  = (const float*)d_in[4];
    const float* Wl2 = (const float*)d_in[5];
    const float* Wr2 = (const float*)d_in[6];
    const float* b2  = (const float*)d_in[7];
    float* out = (float*)d_out;

    cudaFuncSetAttribute(gemm1_mma, cudaFuncAttributeMaxDynamicSharedMemorySize, SMEM_TOT);
    cudaFuncSetAttribute(gemm2_mma, cudaFuncAttributeMaxDynamicSharedMemorySize, SMEM_TOT);

    zero_cnt_kernel<<<(N_NODES + 255) / 256, 256>>>();
    count_kernel<<<(N_EDGES + 255) / 256, 256>>>(ei);
    scan_kernel<<<1, 1024>>>();
    place_kernel<<<(N_EDGES + 255) / 256, 256>>>(ei);
    gather1_kernel<<<(N_NODES * 32 + 255) / 256, 256>>>(x);
    xsplit_kernel<<<(N_NODES * 32 + 255) / 256, 256>>>(x);
    prep_B_kernel<<<(256 * 256 + 128 * 256 + 255) / 256, 256>>>(Wl1, Wr1, Wl2, Wr2);
    {
        dim3 g((N_NODES + 127) / 128, 2);
        gemm1_mma<<<g, 256, SMEM_TOT>>>(b1);
    }
    {
        dim3 g((N_NODES + 127) / 128, 1);
        gemm2_mma<<<g, 256, SMEM_TOT>>>(out);
    }
    gather2_fin_kernel<<<(N_NODES * 32 + 255) / 256, 256>>>(b2, out);
}

// round 17
// speedup vs baseline: 1.9752x; 1.0149x over previous
#include <cuda_runtime.h>
#include <cuda_bf16.h>
#include <cstdint>

#define N_NODES 50000
#define N_EDGES 800000
#define F_IN 128
#define F_HID 256
#define F_OUT 64

typedef unsigned short u16;
typedef unsigned int u32;

// ---------------- scratch ----------------------------------------------------
__device__ __align__(16) u16 g_A1h[N_NODES * 256];   // [m][k]: cols 0-127 mean, 128-255 x (bf16 hi)
__device__ __align__(16) u16 g_A1l[N_NODES * 256];   // bf16 lo
__device__ __align__(16) u16 g_A2h[N_NODES * 256];   // h split hi
__device__ __align__(16) u16 g_A2l[N_NODES * 256];   // h split lo
__device__ __align__(16) u16 g_B1h[256 * 256];       // [n][k] = [W_l1;W_r1]^T hi
__device__ __align__(16) u16 g_B1l[256 * 256];
__device__ __align__(16) u16 g_B2h[128 * 256];       // [n][k] = [W_l2|W_r2]^T hi
__device__ __align__(16) u16 g_B2l[128 * 256];
__device__ __align__(16) float g_p[N_NODES * F_OUT]; // h @ W_l2
__device__ int g_cnt[N_NODES];
__device__ int g_cursor[N_NODES];
__device__ int g_row_ptr[N_NODES + 1];
__device__ int g_csr_src[N_EDGES];

// ---------------- helpers ----------------------------------------------------
__device__ __forceinline__ u32 smem_u32(const void* p) {
    u32 a;
    asm("{ .reg .u64 t; cvta.to.shared.u64 t, %1; cvt.u32.u64 %0, t; }" : "=r"(a) : "l"(p));
    return a;
}
__device__ __forceinline__ u32 lds32(u32 a) {
    u32 v;
    asm volatile("ld.shared.b32 %0, [%1];" : "=r"(v) : "r"(a));
    return v;
}
#define CP16(dst, src, sz)                                                     \
    asm volatile("cp.async.cg.shared.global [%0], [%1], 16, %2;"               \
                 :: "r"(dst), "l"(src), "r"(sz) : "memory")
#define CP_COMMIT() asm volatile("cp.async.commit_group;" ::: "memory")
#define CP_WAIT1()  asm volatile("cp.async.wait_group 1;" ::: "memory")

#define MMA_BF16(d, a, b0v, b1v)                                               \
    asm volatile("mma.sync.aligned.m16n8k16.row.col.f32.bf16.bf16.f32 "        \
                 "{%0,%1,%2,%3}, {%4,%5,%6,%7}, {%8,%9}, {%0,%1,%2,%3};"       \
                 : "+f"((d)[0]), "+f"((d)[1]), "+f"((d)[2]), "+f"((d)[3])      \
                 : "r"((a)[0]), "r"((a)[1]), "r"((a)[2]), "r"((a)[3]),         \
                   "r"(b0v), "r"(b1v))

__device__ __forceinline__ void split_bf16(float f, u16& hi, u16& lo) {
    __nv_bfloat16 h = __float2bfloat16(f);
    float r = f - __bfloat162float(h);
    __nv_bfloat16 l = __float2bfloat16(r);
    hi = __bfloat16_as_ushort(h);
    lo = __bfloat16_as_ushort(l);
}
__device__ __forceinline__ u32 pack_split_hi(float v0, float v1, u32& lopack) {
    u16 h0, l0, h1, l1;
    split_bf16(v0, h0, l0);
    split_bf16(v1, h1, l1);
    lopack = (u32)l0 | ((u32)l1 << 16);
    return (u32)h0 | ((u32)h1 << 16);
}

// ------- fused: zero degree counters + weight transpose/split (launch #1) ---
__global__ void prep_kernel(const float* __restrict__ Wl1, const float* __restrict__ Wr1,
                            const float* __restrict__ Wl2, const float* __restrict__ Wr2) {
    int idx = blockIdx.x * blockDim.x + threadIdx.x;
    if (idx < N_NODES) g_cnt[idx] = 0;
    if (idx < 256 * 256) {
        int n = idx >> 8, k = idx & 255;
        float v = (k < 128) ? Wl1[k * F_HID + n] : Wr1[(k - 128) * F_HID + n];
        u16 hi, lo;
        split_bf16(v, hi, lo);
        g_B1h[n * 256 + k] = hi;
        g_B1l[n * 256 + k] = lo;
    } else if (idx < 256 * 256 + 128 * 256) {
        int r = idx - 256 * 256;
        int n = r >> 8, k = r & 255;
        float v = (n < 64) ? Wl2[k * F_OUT + n] : Wr2[k * F_OUT + (n - 64)];
        u16 hi, lo;
        split_bf16(v, hi, lo);
        g_B2h[n * 256 + k] = hi;
        g_B2l[n * 256 + k] = lo;
    }
}

// ---------------- CSR build --------------------------------------------------
__global__ void count_kernel(const int* __restrict__ ei) {
    int e = blockIdx.x * blockDim.x + threadIdx.x;
    if (e >= N_EDGES) return;
    atomicAdd(&g_cnt[ei[N_EDGES + e]], 1);
}
__global__ __launch_bounds__(1024) void scan_kernel() {
    __shared__ int ssum[1024];
    const int t = threadIdx.x;
    const int CH = (N_NODES + 1023) / 1024;
    int beg = t * CH;
    int end = min(beg + CH, N_NODES);
    int s = 0;
    for (int i = beg; i < end; i++) s += g_cnt[i];
    ssum[t] = s;
    __syncthreads();
    for (int off = 1; off < 1024; off <<= 1) {
        int tmp = (t >= off) ? ssum[t - off] : 0;
        __syncthreads();
        ssum[t] += tmp;
        __syncthreads();
    }
    int base = ssum[t] - s;
    for (int i = beg; i < end; i++) {
        int c = g_cnt[i];
        g_row_ptr[i] = base;
        g_cursor[i] = base;
        base += c;
    }
    if (t == 1023) g_row_ptr[N_NODES] = base;
}
__global__ void place_kernel(const int* __restrict__ ei) {
    int e = blockIdx.x * blockDim.x + threadIdx.x;
    if (e >= N_EDGES) return;
    int src = ei[e];
    int dst = ei[N_EDGES + e];
    int pos = atomicAdd(&g_cursor[dst], 1);
    g_csr_src[pos] = src;
}

// --- layer-1 gather (mean -> cols 0-127) + x copy/split (cols 128-255) -----
// one warp per node; lane owns 4 cols of each half
__global__ __launch_bounds__(256) void gather1_kernel(const float* __restrict__ x) {
    int w = (blockIdx.x * blockDim.x + threadIdx.x) >> 5;
    int lane = threadIdx.x & 31;
    if (w >= N_NODES) return;
    int beg = g_row_ptr[w], end = g_row_ptr[w + 1];
    float4 acc = make_float4(0.f, 0.f, 0.f, 0.f);
    int i = beg;
    for (; i + 1 < end; i += 2) {
        int s0 = __ldg(&g_csr_src[i]);
        int s1 = __ldg(&g_csr_src[i + 1]);
        float4 v0 = __ldg(&((const float4*)x)[s0 * 32 + lane]);
        float4 v1 = __ldg(&((const float4*)x)[s1 * 32 + lane]);
        acc.x += v0.x + v1.x; acc.y += v0.y + v1.y;
        acc.z += v0.z + v1.z; acc.w += v0.w + v1.w;
    }
    if (i < end) {
        int s0 = __ldg(&g_csr_src[i]);
        float4 v0 = __ldg(&((const float4*)x)[s0 * 32 + lane]);
        acc.x += v0.x; acc.y += v0.y; acc.z += v0.z; acc.w += v0.w;
    }
    float inv = (end > beg) ? 1.0f / (float)(end - beg) : 0.f;
    acc.x *= inv; acc.y *= inv; acc.z *= inv; acc.w *= inv;
    {
        u32 l0, l1;
        u32 h0 = pack_split_hi(acc.x, acc.y, l0);
        u32 h1 = pack_split_hi(acc.z, acc.w, l1);
        int o = w * 256 + lane * 4;
        *(uint2*)&g_A1h[o] = make_uint2(h0, h1);
        *(uint2*)&g_A1l[o] = make_uint2(l0, l1);
    }
    // fused xsplit: copy own row x[w] into cols 128-255 (bf16 split)
    {
        float4 xv = __ldg(&((const float4*)x)[w * 32 + lane]);
        u32 l0, l1;
        u32 h0 = pack_split_hi(xv.x, xv.y, l0);
        u32 h1 = pack_split_hi(xv.z, xv.w, l1);
        int o = w * 256 + 128 + lane * 4;
        *(uint2*)&g_A1h[o] = make_uint2(h0, h1);
        *(uint2*)&g_A1l[o] = make_uint2(l0, l1);
    }
}

// ---------------- bf16 mma GEMM core ----------------------------------------
// CTA: 128m x 128n, 8 warps (4m x 2n), warp tile 32m x 64n.
// K = 256 in 8 chunks of 32. smem row = 64B data + 16B pad (80B stride).
// Buffer layout (per buf, 40960B): Ah@0, Al@10240, Bh@20480, Bl@30720.
#define ROWB 80
#define REG 10240
#define BUFB 40960
#define SMEM_TOT (2 * BUFB)

__device__ __forceinline__ void load_chunk(
    u32 sb_buf, int c, int row_base, int bbase,
    const u16* Ah, const u16* Al, const u16* Bh, const u16* Bl, int tid)
{
#pragma unroll
    for (int i = 0; i < 2; i++) {
        int t2 = tid * 2 + i;
        int row = t2 >> 2, q = t2 & 3;
        int gr = row_base + row;
        int szA = (gr < N_NODES) ? 16 : 0;
        int grc = (gr < N_NODES) ? gr : 0;
        u32 d = sb_buf + row * ROWB + q * 16;
        CP16(d,           Ah + grc * 256 + c * 32 + q * 8, szA);
        CP16(d + REG,     Al + grc * 256 + c * 32 + q * 8, szA);
        int bn = bbase + row;
        CP16(d + 2 * REG, Bh + bn * 256 + c * 32 + q * 8, 16);
        CP16(d + 3 * REG, Bl + bn * 256 + c * 32 + q * 8, 16);
    }
}

__device__ __forceinline__ void compute_chunk(
    u32 sb_buf, float (&acc)[2][8][4], int lane, int warp_m, int warp_n)
{
#pragma unroll
    for (int ks = 0; ks < 2; ks++) {
        int kb = ks * 32;   // byte offset of k-step within row
        u32 ah[2][4], al[2][4];
#pragma unroll
        for (int mt = 0; mt < 2; mt++) {
            u32 ab = sb_buf + (warp_m * 32 + mt * 16 + (lane >> 2)) * ROWB + kb + (lane & 3) * 4;
            ah[mt][0] = lds32(ab);
            ah[mt][1] = lds32(ab + 8 * ROWB);
            ah[mt][2] = lds32(ab + 16);
            ah[mt][3] = lds32(ab + 8 * ROWB + 16);
            al[mt][0] = lds32(ab + REG);
            al[mt][1] = lds32(ab + REG + 8 * ROWB);
            al[mt][2] = lds32(ab + REG + 16);
            al[mt][3] = lds32(ab + REG + 8 * ROWB + 16);
        }
#pragma unroll
        for (int nt = 0; nt < 8; nt++) {
            u32 bb = sb_buf + 2 * REG + (warp_n * 64 + nt * 8 + (lane >> 2)) * ROWB + kb + (lane & 3) * 4;
            u32 bh0 = lds32(bb), bh1 = lds32(bb + 16);
            u32 bl0 = lds32(bb + REG), bl1 = lds32(bb + REG + 16);
#pragma unroll
            for (int mt = 0; mt < 2; mt++) {
                MMA_BF16(acc[mt][nt], ah[mt], bh0, bh1);
                MMA_BF16(acc[mt][nt], ah[mt], bl0, bl1);
                MMA_BF16(acc[mt][nt], al[mt], bh0, bh1);
            }
        }
    }
}

#define GEMM_PIPELINE(AH, AL, BH, BL, BBASE)                                   \
    u32 sb = smem_u32(sm);                                                     \
    const int tid = threadIdx.x;                                               \
    const int lane = tid & 31, wid = tid >> 5;                                 \
    const int warp_m = wid & 3, warp_n = wid >> 2;                             \
    const int row_base = blockIdx.x * 128;                                     \
    float acc[2][8][4];                                                        \
    _Pragma("unroll") for (int a_ = 0; a_ < 2; a_++)                           \
    _Pragma("unroll") for (int b_ = 0; b_ < 8; b_++)                           \
    _Pragma("unroll") for (int c_ = 0; c_ < 4; c_++) acc[a_][b_][c_] = 0.f;    \
    load_chunk(sb, 0, row_base, BBASE, AH, AL, BH, BL, tid);                   \
    CP_COMMIT();                                                               \
    load_chunk(sb + BUFB, 1, row_base, BBASE, AH, AL, BH, BL, tid);            \
    CP_COMMIT();                                                               \
    for (int c = 0; c < 8; c++) {                                              \
        CP_WAIT1();                                                            \
        __syncthreads();                                                       \
        compute_chunk(sb + (c & 1) * BUFB, acc, lane, warp_m, warp_n);         \
        __syncthreads();                                                       \
        if (c < 6)                                                             \
            load_chunk(sb + (c & 1) * BUFB, c + 2, row_base, BBASE, AH, AL, BH, BL, tid); \
        CP_COMMIT();                                                           \
    }

// GEMM 1: h = relu(A1 @ B1^T + b1) -> A2 (bf16 split). grid (391, 2).
__global__ __launch_bounds__(256, 2) void gemm1_mma(const float* __restrict__ bias) {
    extern __shared__ char sm[];
    const int cb = blockIdx.y * 128;
    GEMM_PIPELINE(g_A1h, g_A1l, g_B1h, g_B1l, cb)
    // epilogue
#pragma unroll
    for (int mt = 0; mt < 2; mt++) {
#pragma unroll
        for (int nt = 0; nt < 8; nt++) {
            int col = cb + warp_n * 64 + nt * 8 + (lane & 3) * 2;
            float b0 = __ldg(bias + col), b1v = __ldg(bias + col + 1);
            int r0 = row_base + warp_m * 32 + mt * 16 + (lane >> 2);
            if (r0 < N_NODES) {
                float v0 = fmaxf(acc[mt][nt][0] + b0, 0.f);
                float v1 = fmaxf(acc[mt][nt][1] + b1v, 0.f);
                u32 lp, hp = pack_split_hi(v0, v1, lp);
                *(u32*)&g_A2h[r0 * 256 + col] = hp;
                *(u32*)&g_A2l[r0 * 256 + col] = lp;
            }
            int r1 = r0 + 8;
            if (r1 < N_NODES) {
                float v0 = fmaxf(acc[mt][nt][2] + b0, 0.f);
                float v1 = fmaxf(acc[mt][nt][3] + b1v, 0.f);
                u32 lp, hp = pack_split_hi(v0, v1, lp);
                *(u32*)&g_A2h[r1 * 256 + col] = hp;
                *(u32*)&g_A2l[r1 * 256 + col] = lp;
            }
        }
    }
}

// GEMM 2: [p | r] = A2 @ B2^T; p -> g_p, r -> out (pre-sigmoid). grid (391, 1).
__global__ __launch_bounds__(256, 2) void gemm2_mma(float* __restrict__ r_out) {
    extern __shared__ char sm[];
    GEMM_PIPELINE(g_A2h, g_A2l, g_B2h, g_B2l, 0)
#pragma unroll
    for (int mt = 0; mt < 2; mt++) {
#pragma unroll
        for (int nt = 0; nt < 8; nt++) {
            int col = warp_n * 64 + nt * 8 + (lane & 3) * 2;
            int r0 = row_base + warp_m * 32 + mt * 16 + (lane >> 2);
            if (r0 < N_NODES) {
                float2 v = make_float2(acc[mt][nt][0], acc[mt][nt][1]);
                if (col < F_OUT) *(float2*)&g_p[r0 * F_OUT + col] = v;
                else             *(float2*)&r_out[r0 * F_OUT + col - F_OUT] = v;
            }
            int r1 = r0 + 8;
            if (r1 < N_NODES) {
                float2 v = make_float2(acc[mt][nt][2], acc[mt][nt][3]);
                if (col < F_OUT) *(float2*)&g_p[r1 * F_OUT + col] = v;
                else             *(float2*)&r_out[r1 * F_OUT + col - F_OUT] = v;
            }
        }
    }
}

// ------- layer-2 gather + finalize: out = sigmoid(mean(p[N(n)]) + r + b2) ---
__global__ __launch_bounds__(256) void gather2_fin_kernel(
    const float* __restrict__ b2, float* __restrict__ out)
{
    int w = (blockIdx.x * blockDim.x + threadIdx.x) >> 5;
    int lane = threadIdx.x & 31;
    if (w >= N_NODES) return;
    int beg = g_row_ptr[w], end = g_row_ptr[w + 1];
    float2 acc = make_float2(0.f, 0.f);
    int i = beg;
    for (; i + 1 < end; i += 2) {
        int s0 = __ldg(&g_csr_src[i]);
        int s1 = __ldg(&g_csr_src[i + 1]);
        float2 v0 = __ldg(&((const float2*)g_p)[s0 * 32 + lane]);
        float2 v1 = __ldg(&((const float2*)g_p)[s1 * 32 + lane]);
        acc.x += v0.x + v1.x; acc.y += v0.y + v1.y;
    }
    if (i < end) {
        int s0 = __ldg(&g_csr_src[i]);
        float2 v0 = __ldg(&((const float2*)g_p)[s0 * 32 + lane]);
        acc.x += v0.x; acc.y += v0.y;
    }
    float inv = (end > beg) ? 1.0f / (float)(end - beg) : 0.f;
    float2 r = ((const float2*)out)[w * 32 + lane];
    float zx = acc.x * inv + r.x + b2[lane * 2];
    float zy = acc.y * inv + r.y + b2[lane * 2 + 1];
    float2 o;
    o.x = 1.0f / (1.0f + expf(-zx));
    o.y = 1.0f / (1.0f + expf(-zy));
    ((float2*)out)[w * 32 + lane] = o;
}

// ---------------- launch -----------------------------------------------------
extern "C" void kernel_launch(void* const* d_in, const int* in_sizes, int n_in,
                              void* d_out, int out_size) {
    const float* x   = (const float*)d_in[0];
    const int*   ei  = (const int*)d_in[1];
    const float* Wl1 = (const float*)d_in[2];
    const float* Wr1 = (const float*)d_in[3];
    const float* b1  = (const float*)d_in[4];
    const float* Wl2 = (const float*)d_in[5];
    const float* Wr2 = (const float*)d_in[6];
    const float* b2  = (const float*)d_in[7];
    float* out = (float*)d_out;

    cudaFuncSetAttribute(gemm1_mma, cudaFuncAttributeMaxDynamicSharedMemorySize, SMEM_TOT);
    cudaFuncSetAttribute(gemm2_mma, cudaFuncAttributeMaxDynamicSharedMemorySize, SMEM_TOT);

    // launch order places gemm1_mma at slot 6 (ncu -s 5 -c 1 captures it)
    {
        int tot = 256 * 256 + 128 * 256;   // >= N_NODES
        prep_kernel<<<(tot + 255) / 256, 256>>>(Wl1, Wr1, Wl2, Wr2);
    }
    count_kernel<<<(N_EDGES + 255) / 256, 256>>>(ei);
    scan_kernel<<<1, 1024>>>();
    place_kernel<<<(N_EDGES + 255) / 256, 256>>>(ei);
    gather1_kernel<<<(N_NODES * 32 + 255) / 256, 256>>>(x);
    {
        dim3 g((N_NODES + 127) / 128, 2);
        gemm1_mma<<<g, 256, SMEM_TOT>>>(b1);
    }
    {
        dim3 g((N_NODES + 127) / 128, 1);
        gemm2_mma<<<g, 256, SMEM_TOT>>>(out);
    }
    gather2_fin_kernel<<<(N_NODES * 32 + 255) / 256, 256>>>(b2, out);
}